// round 1
// baseline (speedup 1.0000x reference)
#include <cuda_runtime.h>
#include <cstdint>

// Problem constants
#define NROWS   32768
#define DIM     64
#define KCODES  1024
#define KC      128            // codes per smem chunk (32 KB)
#define NCHUNK  (KCODES / KC)
#define CTAS    148
#define TPB     256

// Output layout (flattened fp32): [quantized_st | vq_loss | indices | perplexity]
#define OFF_Q   0
#define OFF_L   2097152
#define OFF_I   2097153
#define OFF_P   2129921

// Scratch (device globals: no allocation allowed)
__device__ float  g_esq[KCODES];
__device__ int    g_counts[KCODES];
__device__ double g_losssum;

// Packed fp32x2 FMA: two exact fp32 FMAs per instruction (PTX-only path)
__device__ __forceinline__ unsigned long long ffma2(unsigned long long a,
                                                    unsigned long long b,
                                                    unsigned long long c) {
    unsigned long long d;
    asm("fma.rn.f32x2 %0, %1, %2, %3;" : "=l"(d) : "l"(a), "l"(b), "l"(c));
    return d;
}
__device__ __forceinline__ float lo32(unsigned long long p) {
    return __uint_as_float((unsigned)p);
}
__device__ __forceinline__ float hi32(unsigned long long p) {
    return __uint_as_float((unsigned)(p >> 32));
}

// ---------------------------------------------------------------------------
// Init: zero histogram + loss accumulator, precompute ||e_k||^2 (fp32, like ref)
// ---------------------------------------------------------------------------
__global__ void vq_init(const float* __restrict__ codebook) {
    int k = blockIdx.x * blockDim.x + threadIdx.x;
    if (k < KCODES) {
        g_counts[k] = 0;
        const float* e = codebook + k * DIM;
        float s = 0.f;
        #pragma unroll
        for (int d = 0; d < DIM; ++d) s = fmaf(e[d], e[d], s);
        g_esq[k] = s;
    }
    if (k == 0) g_losssum = 0.0;
}

// ---------------------------------------------------------------------------
// Main: per-row argmin over 1024 codes, quantized output, index, loss partials
// ---------------------------------------------------------------------------
__global__ __launch_bounds__(TPB, 1) void vq_main(
    const float* __restrict__ z,
    const float* __restrict__ codebook,
    float* __restrict__ out)
{
    __shared__ unsigned long long se[KC * (DIM / 2)];  // 128 codes x 32 f32x2 = 32 KB
    __shared__ float sesq[KC];

    const int tid = threadIdx.x;
    const int r   = blockIdx.x + CTAS * tid;   // balanced row distribution
    const bool active = (r < NROWS);

    // Load this lane's z row into registers (packed pairs), compute ||z||^2
    unsigned long long zp[DIM / 2];
    float zsq = 0.f;
    if (active) {
        const ulonglong2* zr =
            reinterpret_cast<const ulonglong2*>(z + (size_t)r * DIM);
        #pragma unroll
        for (int i = 0; i < DIM / 4; ++i) {
            ulonglong2 t = zr[i];
            zp[2 * i]     = t.x;
            zp[2 * i + 1] = t.y;
        }
        #pragma unroll
        for (int i = 0; i < DIM / 2; ++i) {
            float a = lo32(zp[i]), b = hi32(zp[i]);
            zsq = fmaf(a, a, zsq);
            zsq = fmaf(b, b, zsq);
        }
    }

    float best  = 3.402823466e38f;
    int   bestk = 0;

    for (int c = 0; c < NCHUNK; ++c) {
        __syncthreads();
        // Stage codebook chunk (coalesced float4 copies)
        {
            const float4* src =
                reinterpret_cast<const float4*>(codebook + (size_t)c * KC * DIM);
            float4* dst = reinterpret_cast<float4*>(se);
            #pragma unroll
            for (int i = tid; i < KC * DIM / 4; i += TPB) dst[i] = src[i];
            if (tid < KC) sesq[tid] = g_esq[c * KC + tid];
        }
        __syncthreads();

        if (active) {
            #pragma unroll 1
            for (int kb = 0; kb < KC; kb += 4) {
                const unsigned long long* e0 = se + (kb + 0) * (DIM / 2);
                const unsigned long long* e1 = se + (kb + 1) * (DIM / 2);
                const unsigned long long* e2 = se + (kb + 2) * (DIM / 2);
                const unsigned long long* e3 = se + (kb + 3) * (DIM / 2);
                unsigned long long a0 = 0ull, a1 = 0ull, a2 = 0ull, a3 = 0ull;
                #pragma unroll
                for (int d = 0; d < DIM / 2; ++d) {
                    unsigned long long zd = zp[d];
                    a0 = ffma2(zd, e0[d], a0);
                    a1 = ffma2(zd, e1[d], a1);
                    a2 = ffma2(zd, e2[d], a2);
                    a3 = ffma2(zd, e3[d], a3);
                }
                float m0 = lo32(a0) + hi32(a0);
                float m1 = lo32(a1) + hi32(a1);
                float m2 = lo32(a2) + hi32(a2);
                float m3 = lo32(a3) + hi32(a3);
                // d_k = fl( fl(zsq + esq_k) - 2*mm_k )  (matches reference rounding;
                // 2*mm is exact, so single-rounded fused form is bit-identical)
                float d0 = __fmaf_rn(-2.f, m0, zsq + sesq[kb + 0]);
                float d1 = __fmaf_rn(-2.f, m1, zsq + sesq[kb + 1]);
                float d2 = __fmaf_rn(-2.f, m2, zsq + sesq[kb + 2]);
                float d3 = __fmaf_rn(-2.f, m3, zsq + sesq[kb + 3]);
                int kbase = c * KC + kb;
                // strict < in ascending k == jnp.argmin first-min tie rule
                if (d0 < best) { best = d0; bestk = kbase + 0; }
                if (d1 < best) { best = d1; bestk = kbase + 1; }
                if (d2 < best) { best = d2; bestk = kbase + 2; }
                if (d3 < best) { best = d3; bestk = kbase + 3; }
            }
        }
    }

    // Epilogue: quantized_st (= z + (q - z), fp32-rounded like ref), index, loss
    float lsum = 0.f;
    if (active) {
        const float* eb = codebook + (size_t)bestk * DIM;
        float* oq = out + OFF_Q + (size_t)r * DIM;
        #pragma unroll
        for (int i = 0; i < DIM / 2; ++i) {
            float z0 = lo32(zp[i]), z1 = hi32(zp[i]);
            float q0 = eb[2 * i], q1 = eb[2 * i + 1];
            float df0 = q0 - z0, df1 = q1 - z1;
            oq[2 * i]     = z0 + df0;
            oq[2 * i + 1] = z1 + df1;
            lsum = fmaf(df0, df0, lsum);
            lsum = fmaf(df1, df1, lsum);
        }
        out[OFF_I + r] = (float)bestk;
        atomicAdd(&g_counts[bestk], 1);
    }

    // Warp-reduce loss partial, one double atomic per warp
    #pragma unroll
    for (int off = 16; off; off >>= 1)
        lsum += __shfl_down_sync(0xffffffffu, lsum, off);
    if ((tid & 31) == 0)
        atomicAdd(&g_losssum, (double)lsum);
}

// ---------------------------------------------------------------------------
// Finalize: vq_loss and perplexity scalars
// ---------------------------------------------------------------------------
__global__ void vq_final(float* __restrict__ out) {
    __shared__ double red[32];
    int t = threadIdx.x;  // 1024 threads
    float c = (float)g_counts[t];
    float p = c * (1.0f / 32768.0f);               // exact (power-of-2 divide)
    float term = p * logf(p + 1e-10f);
    double v = (double)term;
    #pragma unroll
    for (int off = 16; off; off >>= 1)
        v += __shfl_down_sync(0xffffffffu, v, off);
    if ((t & 31) == 0) red[t >> 5] = v;
    __syncthreads();
    if (t < 32) {
        double w = red[t];
        #pragma unroll
        for (int off = 16; off; off >>= 1)
            w += __shfl_down_sync(0xffffffffu, w, off);
        if (t == 0) {
            float s = (float)w;
            out[OFF_P] = expf(-s);
            float m = (float)(g_losssum * (1.0 / 2097152.0));  // exact /2^21
            out[OFF_L] = m + 0.25f * m;   // q_latent + 0.25 * e_latent (equal values)
        }
    }
}

// ---------------------------------------------------------------------------
extern "C" void kernel_launch(void* const* d_in, const int* in_sizes, int n_in,
                              void* d_out, int out_size) {
    const float* z        = (const float*)d_in[0];
    const float* codebook = (const float*)d_in[1];
    float* out = (float*)d_out;

    vq_init<<<(KCODES + 255) / 256, 256>>>(codebook);
    vq_main<<<CTAS, TPB>>>(z, codebook, out);
    vq_final<<<1, KCODES>>>(out);
}

// round 2
// speedup vs baseline: 1.0376x; 1.0376x over previous
#include <cuda_runtime.h>
#include <cstdint>

// Problem constants
#define NROWS    32768
#define DIM      64
#define KCODES   1024
#define KC       128           // codes per smem chunk (32 KB)
#define NCHUNK   (KCODES / KC)
#define CTAS     148
#define TPB      256
#define NWBLOCKS 1024          // 32768 rows / 32 lanes

// Output layout (flattened fp32): [quantized_st | vq_loss | indices | perplexity]
#define OFF_Q   0
#define OFF_L   2097152
#define OFF_I   2097153
#define OFF_P   2129921

typedef unsigned long long ull;

// Scratch (device globals: no allocation allowed)
__device__ float  g_esq[KCODES];
__device__ int    g_counts[KCODES];
__device__ double g_losssum;

// Packed fp32x2 FMA: two exact fp32 FMAs per instruction (PTX-only FFMA2 path)
__device__ __forceinline__ ull ffma2(ull a, ull b, ull c) {
    ull d;
    asm("fma.rn.f32x2 %0, %1, %2, %3;" : "=l"(d) : "l"(a), "l"(b), "l"(c));
    return d;
}
__device__ __forceinline__ float lo32(ull p) { return __uint_as_float((unsigned)p); }
__device__ __forceinline__ float hi32(ull p) { return __uint_as_float((unsigned)(p >> 32)); }

// ---------------------------------------------------------------------------
// Prep: warp-per-code ||e_k||^2, zero histogram + loss accumulator
// grid 128 x 256  (1024 warps)
// ---------------------------------------------------------------------------
__global__ void vq_prep(const float* __restrict__ codebook) {
    int gt   = blockIdx.x * blockDim.x + threadIdx.x;
    int wcode = gt >> 5;
    int lane  = gt & 31;
    if (wcode < KCODES) {
        const float2* e = reinterpret_cast<const float2*>(codebook + wcode * DIM);
        float2 v = e[lane];                       // coalesced 256B per warp
        float s = fmaf(v.x, v.x, v.y * v.y);
        #pragma unroll
        for (int off = 16; off; off >>= 1)
            s += __shfl_xor_sync(0xffffffffu, s, off);
        if (lane == 0) g_esq[wcode] = s;
    }
    if (gt < KCODES) g_counts[gt] = 0;
    if (gt == 0) g_losssum = 0.0;
}

// ---------------------------------------------------------------------------
// Main: per-row argmin over 1024 codes + quantized output + loss partials
// grid 148 x 256; warp w of CTA b handles rows [(b + 148*w)*32 + lane]
// ---------------------------------------------------------------------------
__global__ __launch_bounds__(TPB, 1) void vq_main(
    const float* __restrict__ z,
    const float* __restrict__ codebook,
    float* __restrict__ out)
{
    __shared__ __align__(16) ull se[KC * (DIM / 2)];  // 128 codes x 32 f32x2 = 32 KB
    __shared__ float sesq[KC];
    __shared__ int   shist[KCODES];                   // 4 KB

    const int tid  = threadIdx.x;
    const int wid  = tid >> 5;
    const int lane = tid & 31;
    const int wb   = blockIdx.x + CTAS * wid;         // warp row-block
    const bool active = (wb < NWBLOCKS);
    const int r = wb * 32 + lane;

    // z row into registers (packed f32x2), ||z||^2 (same order as round 1)
    ull zp[DIM / 2];
    float zsq = 0.f;
    if (active) {
        const ulonglong2* zr = reinterpret_cast<const ulonglong2*>(z + (size_t)r * DIM);
        #pragma unroll
        for (int i = 0; i < DIM / 4; ++i) {
            ulonglong2 t = zr[i];
            zp[2 * i]     = t.x;
            zp[2 * i + 1] = t.y;
        }
        #pragma unroll
        for (int i = 0; i < DIM / 2; ++i) {
            float a = lo32(zp[i]), b = hi32(zp[i]);
            zsq = fmaf(a, a, zsq);
            zsq = fmaf(b, b, zsq);
        }
    }

    float best  = 3.402823466e38f;
    int   bestk = 0;

    for (int c = 0; c < NCHUNK; ++c) {
        __syncthreads();
        // Stage codebook chunk (coalesced float4 copies), plus esq slice
        {
            const float4* src = reinterpret_cast<const float4*>(codebook + (size_t)c * KC * DIM);
            float4* dst = reinterpret_cast<float4*>(se);
            #pragma unroll
            for (int i = tid; i < KC * DIM / 4; i += TPB) dst[i] = src[i];
            if (tid < KC) sesq[tid] = g_esq[c * KC + tid];
        }
        __syncthreads();

        if (active) {
            #pragma unroll 1
            for (int kb = 0; kb < KC; kb += 4) {
                const ulonglong2* e0 = reinterpret_cast<const ulonglong2*>(se + (kb + 0) * (DIM / 2));
                const ulonglong2* e1 = reinterpret_cast<const ulonglong2*>(se + (kb + 1) * (DIM / 2));
                const ulonglong2* e2 = reinterpret_cast<const ulonglong2*>(se + (kb + 2) * (DIM / 2));
                const ulonglong2* e3 = reinterpret_cast<const ulonglong2*>(se + (kb + 3) * (DIM / 2));
                ull a0 = 0ull, b0 = 0ull, a1 = 0ull, b1 = 0ull;
                ull a2 = 0ull, b2 = 0ull, a3 = 0ull, b3 = 0ull;
                #pragma unroll
                for (int d = 0; d < DIM / 4; ++d) {     // 16 steps of LDS.128
                    ull ze = zp[2 * d], zo = zp[2 * d + 1];
                    ulonglong2 t0 = e0[d];
                    ulonglong2 t1 = e1[d];
                    ulonglong2 t2 = e2[d];
                    ulonglong2 t3 = e3[d];
                    a0 = ffma2(ze, t0.x, a0);  b0 = ffma2(zo, t0.y, b0);
                    a1 = ffma2(ze, t1.x, a1);  b1 = ffma2(zo, t1.y, b1);
                    a2 = ffma2(ze, t2.x, a2);  b2 = ffma2(zo, t2.y, b2);
                    a3 = ffma2(ze, t3.x, a3);  b3 = ffma2(zo, t3.y, b3);
                }
                float m0 = (lo32(a0) + hi32(a0)) + (lo32(b0) + hi32(b0));
                float m1 = (lo32(a1) + hi32(a1)) + (lo32(b1) + hi32(b1));
                float m2 = (lo32(a2) + hi32(a2)) + (lo32(b2) + hi32(b2));
                float m3 = (lo32(a3) + hi32(a3)) + (lo32(b3) + hi32(b3));
                // d_k = fl(fl(zsq + esq_k) - 2*mm_k)  (reference rounding structure)
                float d0 = __fmaf_rn(-2.f, m0, zsq + sesq[kb + 0]);
                float d1 = __fmaf_rn(-2.f, m1, zsq + sesq[kb + 1]);
                float d2 = __fmaf_rn(-2.f, m2, zsq + sesq[kb + 2]);
                float d3 = __fmaf_rn(-2.f, m3, zsq + sesq[kb + 3]);
                int kbase = c * KC + kb;
                // strict < in ascending k == jnp.argmin first-min tie rule
                if (d0 < best) { best = d0; bestk = kbase + 0; }
                if (d1 < best) { best = d1; bestk = kbase + 1; }
                if (d2 < best) { best = d2; bestk = kbase + 2; }
                if (d3 < best) { best = d3; bestk = kbase + 3; }
            }
        }
    }

    // Epilogue: quantized_st, index, loss partials, shared histogram
    __syncthreads();
    #pragma unroll
    for (int i = tid; i < KCODES; i += TPB) shist[i] = 0;
    __syncthreads();

    float lsum = 0.f;
    if (active) {
        const float* eb = codebook + (size_t)bestk * DIM;
        float* oq = out + OFF_Q + (size_t)r * DIM;
        #pragma unroll
        for (int i = 0; i < DIM / 2; ++i) {
            float z0 = lo32(zp[i]), z1 = hi32(zp[i]);
            float q0 = eb[2 * i], q1 = eb[2 * i + 1];
            float df0 = q0 - z0, df1 = q1 - z1;
            oq[2 * i]     = z0 + df0;                 // z + (q - z), ref rounding
            oq[2 * i + 1] = z1 + df1;
            lsum = fmaf(df0, df0, lsum);
            lsum = fmaf(df1, df1, lsum);
        }
        out[OFF_I + r] = (float)bestk;
        atomicAdd(&shist[bestk], 1);
    }
    __syncthreads();
    #pragma unroll
    for (int i = tid; i < KCODES; i += TPB) {
        int cnt = shist[i];
        if (cnt) atomicAdd(&g_counts[i], cnt);
    }

    // Warp-reduce loss partial, one double atomic per warp
    #pragma unroll
    for (int off = 16; off; off >>= 1)
        lsum += __shfl_down_sync(0xffffffffu, lsum, off);
    if (lane == 0 && active)
        atomicAdd(&g_losssum, (double)lsum);
}

// ---------------------------------------------------------------------------
// Finalize: vq_loss and perplexity scalars
// ---------------------------------------------------------------------------
__global__ void vq_final(float* __restrict__ out) {
    __shared__ double red[32];
    int t = threadIdx.x;  // 1024 threads
    float c = (float)g_counts[t];
    float p = c * (1.0f / 32768.0f);               // exact (power-of-2 divide)
    float term = p * logf(p + 1e-10f);
    double v = (double)term;
    #pragma unroll
    for (int off = 16; off; off >>= 1)
        v += __shfl_down_sync(0xffffffffu, v, off);
    if ((t & 31) == 0) red[t >> 5] = v;
    __syncthreads();
    if (t < 32) {
        double w = red[t];
        #pragma unroll
        for (int off = 16; off; off >>= 1)
            w += __shfl_down_sync(0xffffffffu, w, off);
        if (t == 0) {
            float s = (float)w;
            out[OFF_P] = expf(-s);
            float m = (float)(g_losssum * (1.0 / 2097152.0));  // exact /2^21
            out[OFF_L] = m + 0.25f * m;   // q_latent + 0.25 * e_latent (equal)
        }
    }
}

// Tiny no-op to align vq_main with ncu's -s 5 -c 1 capture window
__global__ void vq_noop() {}

// ---------------------------------------------------------------------------
extern "C" void kernel_launch(void* const* d_in, const int* in_sizes, int n_in,
                              void* d_out, int out_size) {
    const float* z        = (const float*)d_in[0];
    const float* codebook = (const float*)d_in[1];
    float* out = (float*)d_out;

    vq_prep<<<128, 256>>>(codebook);        // launch idx 0 (mod 4)
    vq_main<<<CTAS, TPB>>>(z, codebook, out); // launch idx 1 (mod 4) -> ncu idx 5
    vq_final<<<1, KCODES>>>(out);           // launch idx 2 (mod 4)
    vq_noop<<<1, 32>>>();                   // launch idx 3 (mod 4)
}

// round 9
// speedup vs baseline: 1.1272x; 1.0864x over previous
#include <cuda_runtime.h>
#include <cuda_bf16.h>
#include <cstdint>

// ---------------------------------------------------------------- problem
#define NROWS    32768
#define DIM      64
#define KCODES   1024
#define MTILE    128            // rows per CTA
#define NC       64             // codes per chunk
#define NCHUNK   (KCODES / NC)  // 16
#define NCTAS    (NROWS / MTILE)  // 256
#define TPB      128
#define TAU      5e-5f
#define CAP      16

// Output layout (flattened fp32): [quantized_st | vq_loss | indices | perplexity]
#define OFF_Q   0
#define OFF_L   2097152
#define OFF_I   2097153
#define OFF_P   2129921

// ---------------------------------------------------------------- smem layout
#define RSA 144                 // bf16 tile row stride (bytes): conflict-free frags
#define RSS 272                 // score tile row stride (bytes): 16B-aligned rows

#define SM_AHI   0
#define SM_ALO   (SM_AHI + MTILE * RSA)     // 18432
#define SM_BHI   (SM_ALO + MTILE * RSA)     // 36864
#define SM_BLO   (SM_BHI + NC * RSA)        // 46080
#define SM_SC    (SM_BLO + NC * RSA)        // 55296
#define SM_ESQ   (SM_SC + MTILE * RSS)      // 90112
#define SM_HIST  (SM_ESQ + KCODES * 4)      // 94208
#define SM_TOTAL (SM_HIST + KCODES * 4)     // 98304 (2 CTAs/SM fits 227KB)

// ---------------------------------------------------------------- scratch
__device__ __align__(16) __nv_bfloat16 g_zhi[NROWS * DIM];
__device__ __align__(16) __nv_bfloat16 g_zlo[NROWS * DIM];
__device__ __align__(16) __nv_bfloat16 g_ehi[KCODES * DIM];
__device__ __align__(16) __nv_bfloat16 g_elo[KCODES * DIM];
__device__ float  g_esq[KCODES];
__device__ int    g_counts[KCODES];
__device__ double g_losssum;

// m16n8k16 bf16 MMA, fp32 accumulate (base sm_80+ PTX — assembles at compute_103)
__device__ __forceinline__ void mma16816(float (&c)[4],
                                         uint32_t a0, uint32_t a1, uint32_t a2, uint32_t a3,
                                         uint32_t b0, uint32_t b1) {
    asm("mma.sync.aligned.m16n8k16.row.col.f32.bf16.bf16.f32 "
        "{%0,%1,%2,%3}, {%4,%5,%6,%7}, {%8,%9}, {%0,%1,%2,%3};"
        : "+f"(c[0]), "+f"(c[1]), "+f"(c[2]), "+f"(c[3])
        : "r"(a0), "r"(a1), "r"(a2), "r"(a3), "r"(b0), "r"(b1));
}

// ---------------------------------------------------------------- prep kernels
__global__ void vq_prep_z(const float* __restrict__ z, int half) {
    int i = half * (NROWS * DIM / 2) + blockIdx.x * 256 + threadIdx.x;
    float v = z[i];
    __nv_bfloat16 h = __float2bfloat16(v);
    g_zhi[i] = h;
    g_zlo[i] = __float2bfloat16(v - __bfloat162float(h));
}

__global__ void vq_prep_cb(const float* __restrict__ codebook) {
    int i = blockIdx.x * 256 + threadIdx.x;   // 65536 threads
    float v = codebook[i];
    __nv_bfloat16 h = __float2bfloat16(v);
    g_ehi[i] = h;
    g_elo[i] = __float2bfloat16(v - __bfloat162float(h));
    int wcode = i >> 5, lane = i & 31;
    if (wcode < KCODES) {
        const float2* e = reinterpret_cast<const float2*>(codebook + wcode * DIM);
        float2 t = e[lane];
        float s = fmaf(t.x, t.x, t.y * t.y);
        #pragma unroll
        for (int off = 16; off; off >>= 1)
            s += __shfl_xor_sync(0xffffffffu, s, off);
        if (lane == 0) g_esq[wcode] = s;
    }
    if (i < KCODES) g_counts[i] = 0;
    if (i == 0) g_losssum = 0.0;
}

// ---------------------------------------------------------------- main
__global__ __launch_bounds__(TPB, 2) void vq_main(
    const float* __restrict__ z,
    const float* __restrict__ codebook,
    float* __restrict__ out)
{
    extern __shared__ char smem[];
    const int tid  = threadIdx.x;
    const int wid  = tid >> 5;
    const int lane = tid & 31;
    const int g    = lane >> 2;     // groupID
    const int tg   = lane & 3;      // threadID in group
    const int row0 = blockIdx.x * MTILE;
    const int R    = 32 * wid;      // warp's local row base

    float* sesq  = reinterpret_cast<float*>(smem + SM_ESQ);
    int*   shist = reinterpret_cast<int*>(smem + SM_HIST);

    // ---- stage A (z hi/lo, 128 rows), esq, hist
    {
        const uint4* shi = reinterpret_cast<const uint4*>(g_zhi + (size_t)row0 * DIM);
        const uint4* slo = reinterpret_cast<const uint4*>(g_zlo + (size_t)row0 * DIM);
        #pragma unroll
        for (int i = tid; i < MTILE * 8; i += TPB) {
            int rw = i >> 3, kc = i & 7;
            *reinterpret_cast<uint4*>(smem + SM_AHI + rw * RSA + kc * 16) = shi[i];
            *reinterpret_cast<uint4*>(smem + SM_ALO + rw * RSA + kc * 16) = slo[i];
        }
        #pragma unroll
        for (int i = tid; i < KCODES; i += TPB) { sesq[i] = g_esq[i]; shist[i] = 0; }
    }

    float smin = 3.402823466e38f;
    int   ncand = 0;
    bool  ovf = false;
    int   ck[CAP];
    float cs[CAP];

#define TRY_INSERT(kk, ss) do {                                               \
    if ((ss) <= smin + TAU) {                                                 \
        if (ncand < CAP) { ck[ncand] = (kk); cs[ncand] = (ss); ++ncand; }     \
        else {                                                                 \
            int m = 0;                                                         \
            for (int ii = 0; ii < CAP; ++ii)                                   \
                if (cs[ii] <= smin + TAU) { ck[m] = ck[ii]; cs[m] = cs[ii]; ++m; } \
            ncand = m;                                                         \
            if (ncand < CAP) { ck[ncand] = (kk); cs[ncand] = (ss); ++ncand; }  \
            else ovf = true;                                                   \
        }                                                                      \
    } } while (0)

    for (int c = 0; c < NCHUNK; ++c) {
        __syncthreads();   // all warps done with previous B / scores
        // ---- stage B chunk (64 codes hi/lo)
        {
            const uint4* bhi = reinterpret_cast<const uint4*>(g_ehi + (size_t)c * NC * DIM);
            const uint4* blo = reinterpret_cast<const uint4*>(g_elo + (size_t)c * NC * DIM);
            #pragma unroll
            for (int i = tid; i < NC * 8; i += TPB) {
                int rw = i >> 3, kc = i & 7;
                *reinterpret_cast<uint4*>(smem + SM_BHI + rw * RSA + kc * 16) = bhi[i];
                *reinterpret_cast<uint4*>(smem + SM_BLO + rw * RSA + kc * 16) = blo[i];
            }
        }
        __syncthreads();

        // ---- 3-pass MMA: acc = zhi·ehi + zlo·ehi + zhi·elo  (fp32 accum)
        float acc[2][8][4];
        #pragma unroll
        for (int rt = 0; rt < 2; ++rt)
            #pragma unroll
            for (int j = 0; j < 8; ++j)
                #pragma unroll
                for (int q = 0; q < 4; ++q) acc[rt][j][q] = 0.f;

        #pragma unroll
        for (int t = 0; t < 4; ++t) {                 // k-steps of 16
            uint32_t ahi[2][4], alo[2][4];
            #pragma unroll
            for (int rt = 0; rt < 2; ++rt) {
                uint32_t off = (uint32_t)(R + 16 * rt + g) * RSA + (16 * t + 2 * tg) * 2;
                ahi[rt][0] = *reinterpret_cast<const uint32_t*>(smem + SM_AHI + off);
                ahi[rt][1] = *reinterpret_cast<const uint32_t*>(smem + SM_AHI + off + 8 * RSA);
                ahi[rt][2] = *reinterpret_cast<const uint32_t*>(smem + SM_AHI + off + 16);
                ahi[rt][3] = *reinterpret_cast<const uint32_t*>(smem + SM_AHI + off + 8 * RSA + 16);
                alo[rt][0] = *reinterpret_cast<const uint32_t*>(smem + SM_ALO + off);
                alo[rt][1] = *reinterpret_cast<const uint32_t*>(smem + SM_ALO + off + 8 * RSA);
                alo[rt][2] = *reinterpret_cast<const uint32_t*>(smem + SM_ALO + off + 16);
                alo[rt][3] = *reinterpret_cast<const uint32_t*>(smem + SM_ALO + off + 8 * RSA + 16);
            }
            #pragma unroll
            for (int j = 0; j < 8; ++j) {             // n-tiles of 8 codes
                uint32_t boff = (uint32_t)(8 * j + g) * RSA + (16 * t + 2 * tg) * 2;
                uint32_t bh0 = *reinterpret_cast<const uint32_t*>(smem + SM_BHI + boff);
                uint32_t bh1 = *reinterpret_cast<const uint32_t*>(smem + SM_BHI + boff + 16);
                uint32_t bl0 = *reinterpret_cast<const uint32_t*>(smem + SM_BLO + boff);
                uint32_t bl1 = *reinterpret_cast<const uint32_t*>(smem + SM_BLO + boff + 16);
                #pragma unroll
                for (int rt = 0; rt < 2; ++rt) {
                    mma16816(acc[rt][j], ahi[rt][0], ahi[rt][1], ahi[rt][2], ahi[rt][3], bh0, bh1);
                    mma16816(acc[rt][j], alo[rt][0], alo[rt][1], alo[rt][2], alo[rt][3], bh0, bh1);
                    mma16816(acc[rt][j], ahi[rt][0], ahi[rt][1], ahi[rt][2], ahi[rt][3], bl0, bl1);
                }
            }
        }

        // ---- transpose scores via smem (warp-local rows)
        #pragma unroll
        for (int rt = 0; rt < 2; ++rt) {
            #pragma unroll
            for (int j = 0; j < 8; ++j) {
                uint32_t r0 = (uint32_t)(R + 16 * rt + g);
                uint32_t coff = (uint32_t)(8 * j + 2 * tg) * 4;
                *reinterpret_cast<float2*>(smem + SM_SC + r0 * RSS + coff) =
                    make_float2(acc[rt][j][0], acc[rt][j][1]);
                *reinterpret_cast<float2*>(smem + SM_SC + (r0 + 8) * RSS + coff) =
                    make_float2(acc[rt][j][2], acc[rt][j][3]);
            }
        }
        __syncwarp();

        // ---- scan own row: pass 1 chunk-min, pass 2 insert (tight threshold)
        {
            const float4* srow = reinterpret_cast<const float4*>(smem + SM_SC + (uint32_t)tid * RSS);
            const float4* erow = reinterpret_cast<const float4*>(sesq + c * NC);
            float cmin = 3.402823466e38f;
            #pragma unroll
            for (int q = 0; q < 16; ++q) {
                float4 m4 = srow[q]; float4 e4 = erow[q];
                cmin = fminf(cmin, fmaf(-2.f, m4.x, e4.x));
                cmin = fminf(cmin, fmaf(-2.f, m4.y, e4.y));
                cmin = fminf(cmin, fmaf(-2.f, m4.z, e4.z));
                cmin = fminf(cmin, fmaf(-2.f, m4.w, e4.w));
            }
            smin = fminf(smin, cmin);
            #pragma unroll
            for (int q = 0; q < 16; ++q) {
                float4 m4 = srow[q]; float4 e4 = erow[q];
                int k0 = c * NC + 4 * q;
                float s;
                s = fmaf(-2.f, m4.x, e4.x); TRY_INSERT(k0 + 0, s);
                s = fmaf(-2.f, m4.y, e4.y); TRY_INSERT(k0 + 1, s);
                s = fmaf(-2.f, m4.z, e4.z); TRY_INSERT(k0 + 2, s);
                s = fmaf(-2.f, m4.w, e4.w); TRY_INSERT(k0 + 3, s);
            }
        }
    }

    // ---------------- exact refinement (reference fp32 rounding, R1/R2-proven)
    const int r = row0 + tid;
    float zq[DIM];
    {
        const float4* zr = reinterpret_cast<const float4*>(z + (size_t)r * DIM);
        #pragma unroll
        for (int i = 0; i < DIM / 4; ++i) {
            float4 t = zr[i];
            zq[4 * i] = t.x; zq[4 * i + 1] = t.y; zq[4 * i + 2] = t.z; zq[4 * i + 3] = t.w;
        }
    }
    float zsq = 0.f;
    #pragma unroll
    for (int i = 0; i < DIM; ++i) zsq = fmaf(zq[i], zq[i], zsq);

    float best = 3.402823466e38f;
    int   bestk = 0;
    if (!ovf) {
        for (int i = 0; i < ncand; ++i) {
            if (cs[i] > smin + TAU) continue;
            int k = ck[i];
            const float* e = codebook + (size_t)k * DIM;
            float m = 0.f;
            #pragma unroll
            for (int d = 0; d < DIM; ++d) m = fmaf(zq[d], e[d], m);
            float dd = __fmaf_rn(-2.f, m, zsq + sesq[k]);
            if (dd < best) { best = dd; bestk = k; }   // ascending k, strict <
        }
    } else {
        for (int k = 0; k < KCODES; ++k) {
            const float* e = codebook + (size_t)k * DIM;
            float m = 0.f;
            #pragma unroll
            for (int d = 0; d < DIM; ++d) m = fmaf(zq[d], e[d], m);
            float dd = __fmaf_rn(-2.f, m, zsq + sesq[k]);
            if (dd < best) { best = dd; bestk = k; }
        }
    }

    // ---------------- outputs
    float lsum = 0.f;
    {
        const float* eb = codebook + (size_t)bestk * DIM;
        float* oq = out + OFF_Q + (size_t)r * DIM;
        #pragma unroll
        for (int i = 0; i < DIM; ++i) {
            float df = eb[i] - zq[i];
            oq[i] = zq[i] + df;                 // z + (q - z), ref rounding
            lsum = fmaf(df, df, lsum);
        }
        out[OFF_I + r] = (float)bestk;
        atomicAdd(&shist[bestk], 1);
    }
    __syncthreads();
    #pragma unroll
    for (int i = tid; i < KCODES; i += TPB) {
        int cnt = shist[i];
        if (cnt) atomicAdd(&g_counts[i], cnt);
    }
    #pragma unroll
    for (int off = 16; off; off >>= 1)
        lsum += __shfl_down_sync(0xffffffffu, lsum, off);
    if (lane == 0) atomicAdd(&g_losssum, (double)lsum);
}

// ---------------------------------------------------------------- finalize
__global__ void vq_final(float* __restrict__ out) {
    __shared__ double red[32];
    int t = threadIdx.x;  // 1024 threads
    float c = (float)g_counts[t];
    float p = c * (1.0f / 32768.0f);
    float term = p * logf(p + 1e-10f);
    double v = (double)term;
    #pragma unroll
    for (int off = 16; off; off >>= 1)
        v += __shfl_down_sync(0xffffffffu, v, off);
    if ((t & 31) == 0) red[t >> 5] = v;
    __syncthreads();
    if (t < 32) {
        double w = red[t];
        #pragma unroll
        for (int off = 16; off; off >>= 1)
            w += __shfl_down_sync(0xffffffffu, w, off);
        if (t == 0) {
            float s = (float)w;
            out[OFF_P] = expf(-s);
            float m = (float)(g_losssum * (1.0 / 2097152.0));
            out[OFF_L] = m + 0.25f * m;
        }
    }
}

// ---------------------------------------------------------------- launch
extern "C" void kernel_launch(void* const* d_in, const int* in_sizes, int n_in,
                              void* d_out, int out_size) {
    const float* z        = (const float*)d_in[0];
    const float* codebook = (const float*)d_in[1];
    float* out = (float*)d_out;

    cudaFuncSetAttribute(vq_main, cudaFuncAttributeMaxDynamicSharedMemorySize, SM_TOTAL);

    vq_prep_z<<<4096, 256>>>(z, 0);                       // idx 0
    vq_prep_z<<<4096, 256>>>(z, 1);                       // idx 1
    vq_prep_cb<<<256, 256>>>(codebook);                   // idx 2
    vq_main<<<NCTAS, TPB, SM_TOTAL>>>(z, codebook, out);  // idx 3 (ncu slot)
    vq_final<<<1, KCODES>>>(out);                         // idx 4
}

// round 11
// speedup vs baseline: 1.4609x; 1.2960x over previous
#include <cuda_runtime.h>
#include <cuda_bf16.h>
#include <cstdint>

// ---------------------------------------------------------------- problem
#define NROWS    32768
#define DIM      64
#define KCODES   1024
#define MTILE    128             // rows per CTA
#define NC       64              // codes per chunk
#define NCHUNK   (KCODES / NC)   // 16
#define NCTAS    (NROWS / MTILE) // 256
#define TPB      256             // 8 warps, 16 rows each
#define TAU      5e-5f
#define CAP      8               // per-lane (covers a 512-code subset)

// Output layout (flattened fp32): [quantized_st | vq_loss | indices | perplexity]
#define OFF_Q   0
#define OFF_L   2097152
#define OFF_I   2097153
#define OFF_P   2129921

// ---------------------------------------------------------------- smem layout
#define RSA 144                  // bf16 tile row stride (bytes): conflict-free frags
#define RSS 272                  // score tile row stride (bytes)

#define SM_AHI   0
#define SM_ALO   (SM_AHI + MTILE * RSA)      // 18432
#define SM_B0    (SM_ALO + MTILE * RSA)      // 36864
#define BHALF    (NC * RSA)                  // 9216 (hi or lo)
#define BBUF     (2 * BHALF)                 // 18432 per buffer
#define SM_SC    (SM_B0 + 2 * BBUF)          // 73728
#define SM_ESQ   (SM_SC + MTILE * RSS)       // 108544
#define SM_TOTAL (SM_ESQ + KCODES * 4)       // 112640  (2 CTAs/SM: 225280 <= 227KB)

// ---------------------------------------------------------------- scratch
__device__ __align__(16) __nv_bfloat16 g_zhi[NROWS * DIM];
__device__ __align__(16) __nv_bfloat16 g_zlo[NROWS * DIM];
__device__ __align__(16) __nv_bfloat16 g_ehi[KCODES * DIM];
__device__ __align__(16) __nv_bfloat16 g_elo[KCODES * DIM];
__device__ float  g_esq[KCODES];
__device__ int    g_counts[KCODES];
__device__ double g_losssum;

// m16n8k16 bf16 MMA, fp32 accumulate (base sm_80+ PTX)
__device__ __forceinline__ void mma16816(float (&c)[4],
                                         uint32_t a0, uint32_t a1, uint32_t a2, uint32_t a3,
                                         uint32_t b0, uint32_t b1) {
    asm("mma.sync.aligned.m16n8k16.row.col.f32.bf16.bf16.f32 "
        "{%0,%1,%2,%3}, {%4,%5,%6,%7}, {%8,%9}, {%0,%1,%2,%3};"
        : "+f"(c[0]), "+f"(c[1]), "+f"(c[2]), "+f"(c[3])
        : "r"(a0), "r"(a1), "r"(a2), "r"(a3), "r"(b0), "r"(b1));
}
__device__ __forceinline__ uint32_t lds32(const char* p) {
    return *reinterpret_cast<const uint32_t*>(p);
}

// ---------------------------------------------------------------- prep kernels
__global__ void vq_prep_z(const float* __restrict__ z, int half) {
    int i = half * (NROWS * DIM / 2) + blockIdx.x * 256 + threadIdx.x;
    float v = z[i];
    __nv_bfloat16 h = __float2bfloat16(v);
    g_zhi[i] = h;
    g_zlo[i] = __float2bfloat16(v - __bfloat162float(h));
}

__global__ void vq_prep_cb(const float* __restrict__ codebook) {
    int i = blockIdx.x * 256 + threadIdx.x;   // 65536 threads
    float v = codebook[i];
    __nv_bfloat16 h = __float2bfloat16(v);
    g_ehi[i] = h;
    g_elo[i] = __float2bfloat16(v - __bfloat162float(h));
    int wcode = i >> 5, lane = i & 31;
    if (wcode < KCODES) {
        const float2* e = reinterpret_cast<const float2*>(codebook + wcode * DIM);
        float2 t = e[lane];
        float s = fmaf(t.x, t.x, t.y * t.y);
        #pragma unroll
        for (int off = 16; off; off >>= 1)
            s += __shfl_xor_sync(0xffffffffu, s, off);
        if (lane == 0) g_esq[wcode] = s;
    }
    if (i < KCODES) g_counts[i] = 0;
    if (i == 0) g_losssum = 0.0;
}

// ---------------------------------------------------------------- main
__global__ __launch_bounds__(TPB, 2) void vq_main(
    const float* __restrict__ z,
    const float* __restrict__ codebook,
    float* __restrict__ out)
{
    extern __shared__ char smem[];
    const int tid  = threadIdx.x;
    const int wid  = tid >> 5;
    const int lane = tid & 31;
    const int g    = lane >> 2;     // groupID
    const int tg   = lane & 3;      // threadID in group
    const int row0 = blockIdx.x * MTILE;

    float* sesq = reinterpret_cast<float*>(smem + SM_ESQ);

    // ---- stage A (z hi/lo, 128 rows) + esq; stage B chunk 0 into buf0
    {
        const uint4* shi = reinterpret_cast<const uint4*>(g_zhi + (size_t)row0 * DIM);
        const uint4* slo = reinterpret_cast<const uint4*>(g_zlo + (size_t)row0 * DIM);
        #pragma unroll
        for (int i = tid; i < MTILE * 8; i += TPB) {
            int rw = i >> 3, kc = i & 7;
            *reinterpret_cast<uint4*>(smem + SM_AHI + rw * RSA + kc * 16) = shi[i];
            *reinterpret_cast<uint4*>(smem + SM_ALO + rw * RSA + kc * 16) = slo[i];
        }
        const uint4* bhi = reinterpret_cast<const uint4*>(g_ehi);
        const uint4* blo = reinterpret_cast<const uint4*>(g_elo);
        #pragma unroll
        for (int i = tid; i < NC * 8; i += TPB) {
            int rw = i >> 3, kc = i & 7;
            *reinterpret_cast<uint4*>(smem + SM_B0 + rw * RSA + kc * 16) = bhi[i];
            *reinterpret_cast<uint4*>(smem + SM_B0 + BHALF + rw * RSA + kc * 16) = blo[i];
        }
        #pragma unroll
        for (int i = tid; i < KCODES; i += TPB) sesq[i] = g_esq[i];
    }
    __syncthreads();

    // per-lane candidate state (lane pair shares a row; half = lane&1)
    const int lrow = 16 * wid + (lane >> 1);   // local row this lane scans
    const int half = lane & 1;
    float smin = 3.402823466e38f;
    int   ncand = 0;
    bool  ovf = false;
    int   ck[CAP];
    float cs[CAP];

#define TRY_INSERT(kk, ss) do {                                               \
    if ((ss) <= smin + TAU) {                                                 \
        if (ncand < CAP) { ck[ncand] = (kk); cs[ncand] = (ss); ++ncand; }     \
        else {                                                                 \
            int m_ = 0;                                                        \
            for (int ii = 0; ii < CAP; ++ii)                                   \
                if (cs[ii] <= smin + TAU) { ck[m_] = ck[ii]; cs[m_] = cs[ii]; ++m_; } \
            ncand = m_;                                                        \
            if (ncand < CAP) { ck[ncand] = (kk); cs[ncand] = (ss); ++ncand; }  \
            else ovf = true;                                                   \
        }                                                                      \
    } } while (0)

    for (int c = 0; c < NCHUNK; ++c) {
        // ---- prefetch chunk c+1 into registers (latency overlapped)
        uint4 ph0, ph1, pl0, pl1;
        if (c + 1 < NCHUNK) {
            const uint4* bhi = reinterpret_cast<const uint4*>(g_ehi + (size_t)(c + 1) * NC * DIM);
            const uint4* blo = reinterpret_cast<const uint4*>(g_elo + (size_t)(c + 1) * NC * DIM);
            ph0 = bhi[tid]; ph1 = bhi[tid + TPB];
            pl0 = blo[tid]; pl1 = blo[tid + TPB];
        }

        const char* BHI = smem + SM_B0 + (c & 1) * BBUF;
        const char* BLO = BHI + BHALF;

        // ---- 3-pass MMA: acc = zhi*ehi + zlo*ehi + zhi*elo (fp32 accum)
        float acc[8][4];
        #pragma unroll
        for (int j = 0; j < 8; ++j)
            #pragma unroll
            for (int q = 0; q < 4; ++q) acc[j][q] = 0.f;

        #pragma unroll
        for (int t = 0; t < 4; ++t) {
            // k-step t spans bytes [32t, 32t+32) of the 128-byte bf16 row
            const uint32_t aoff = (uint32_t)(16 * wid + g) * RSA + 32 * t + 4 * tg;
            uint32_t ah[4], al[4];
            ah[0] = lds32(smem + SM_AHI + aoff);
            ah[1] = lds32(smem + SM_AHI + aoff + 8 * RSA);
            ah[2] = lds32(smem + SM_AHI + aoff + 16);
            ah[3] = lds32(smem + SM_AHI + aoff + 8 * RSA + 16);
            al[0] = lds32(smem + SM_ALO + aoff);
            al[1] = lds32(smem + SM_ALO + aoff + 8 * RSA);
            al[2] = lds32(smem + SM_ALO + aoff + 16);
            al[3] = lds32(smem + SM_ALO + aoff + 8 * RSA + 16);

            #pragma unroll
            for (int jb = 0; jb < 2; ++jb) {
                uint32_t bh[4][2], bl[4][2];
                #pragma unroll
                for (int jj = 0; jj < 4; ++jj) {
                    uint32_t boff = (uint32_t)(8 * (4 * jb + jj) + g) * RSA + 32 * t + 4 * tg;
                    bh[jj][0] = lds32(BHI + boff);
                    bh[jj][1] = lds32(BHI + boff + 16);
                    bl[jj][0] = lds32(BLO + boff);
                    bl[jj][1] = lds32(BLO + boff + 16);
                }
                // pass-major: dependent MMAs on same acc are 4 apart
                #pragma unroll
                for (int jj = 0; jj < 4; ++jj)
                    mma16816(acc[4 * jb + jj], ah[0], ah[1], ah[2], ah[3], bh[jj][0], bh[jj][1]);
                #pragma unroll
                for (int jj = 0; jj < 4; ++jj)
                    mma16816(acc[4 * jb + jj], al[0], al[1], al[2], al[3], bh[jj][0], bh[jj][1]);
                #pragma unroll
                for (int jj = 0; jj < 4; ++jj)
                    mma16816(acc[4 * jb + jj], ah[0], ah[1], ah[2], ah[3], bl[jj][0], bl[jj][1]);
            }
        }

        // ---- transpose scores via smem (warp-local rows 16*wid..16*wid+15)
        #pragma unroll
        for (int j = 0; j < 8; ++j) {
            uint32_t r0 = (uint32_t)(16 * wid + g);
            uint32_t coff = (uint32_t)(8 * j + 2 * tg) * 4;
            *reinterpret_cast<float2*>(smem + SM_SC + r0 * RSS + coff) =
                make_float2(acc[j][0], acc[j][1]);
            *reinterpret_cast<float2*>(smem + SM_SC + (r0 + 8) * RSS + coff) =
                make_float2(acc[j][2], acc[j][3]);
        }
        __syncwarp();

        // ---- scan half-row: 32 codes (pass 1 chunk-min, pass 2 insert)
        {
            const float4* srow = reinterpret_cast<const float4*>(
                smem + SM_SC + (uint32_t)lrow * RSS + half * 128);
            const float4* erow = reinterpret_cast<const float4*>(sesq + c * NC + half * 32);
            float cmin = 3.402823466e38f;
            #pragma unroll
            for (int q = 0; q < 8; ++q) {
                float4 m4 = srow[q]; float4 e4 = erow[q];
                cmin = fminf(cmin, fmaf(-2.f, m4.x, e4.x));
                cmin = fminf(cmin, fmaf(-2.f, m4.y, e4.y));
                cmin = fminf(cmin, fmaf(-2.f, m4.z, e4.z));
                cmin = fminf(cmin, fmaf(-2.f, m4.w, e4.w));
            }
            smin = fminf(smin, cmin);
            #pragma unroll
            for (int q = 0; q < 8; ++q) {
                float4 m4 = srow[q]; float4 e4 = erow[q];
                int k0 = c * NC + half * 32 + 4 * q;
                float s;
                s = fmaf(-2.f, m4.x, e4.x); TRY_INSERT(k0 + 0, s);
                s = fmaf(-2.f, m4.y, e4.y); TRY_INSERT(k0 + 1, s);
                s = fmaf(-2.f, m4.z, e4.z); TRY_INSERT(k0 + 2, s);
                s = fmaf(-2.f, m4.w, e4.w); TRY_INSERT(k0 + 3, s);
            }
        }

        // ---- store prefetched chunk into the other buffer, then one sync
        if (c + 1 < NCHUNK) {
            char* DHI = smem + SM_B0 + ((c + 1) & 1) * BBUF;
            int i0 = tid, i1 = tid + TPB;
            *reinterpret_cast<uint4*>(DHI + (i0 >> 3) * RSA + (i0 & 7) * 16) = ph0;
            *reinterpret_cast<uint4*>(DHI + (i1 >> 3) * RSA + (i1 & 7) * 16) = ph1;
            *reinterpret_cast<uint4*>(DHI + BHALF + (i0 >> 3) * RSA + (i0 & 7) * 16) = pl0;
            *reinterpret_cast<uint4*>(DHI + BHALF + (i1 >> 3) * RSA + (i1 & 7) * 16) = pl1;
        }
        __syncthreads();
    }

    // ---------------- exact refinement (reference fp32 rounding, R1/R2-proven)
    const int r = row0 + lrow;
    float zq[DIM];
    {
        const float4* zr = reinterpret_cast<const float4*>(z + (size_t)r * DIM);
        #pragma unroll
        for (int i = 0; i < DIM / 4; ++i) {
            float4 t = zr[i];
            zq[4 * i] = t.x; zq[4 * i + 1] = t.y; zq[4 * i + 2] = t.z; zq[4 * i + 3] = t.w;
        }
    }
    float zsq = 0.f;
    #pragma unroll
    for (int i = 0; i < DIM; ++i) zsq = fmaf(zq[i], zq[i], zsq);

    float best = 3.402823466e38f;
    int   bestk = KCODES;
    if (!ovf) {
        for (int i = 0; i < ncand; ++i) {
            if (cs[i] > smin + TAU) continue;
            int k = ck[i];
            const float* e = codebook + (size_t)k * DIM;
            float m = 0.f;
            #pragma unroll
            for (int d = 0; d < DIM; ++d) m = fmaf(zq[d], e[d], m);
            float dd = __fmaf_rn(-2.f, m, zsq + sesq[k]);
            if (dd < best || (dd == best && k < bestk)) { best = dd; bestk = k; }
        }
    } else {
        // exact scan over this lane's own 512-code subset
        for (int blk = 0; blk < NCHUNK; ++blk) {
            int kb = blk * NC + half * 32;
            for (int kk = 0; kk < 32; ++kk) {
                int k = kb + kk;
                const float* e = codebook + (size_t)k * DIM;
                float m = 0.f;
                #pragma unroll
                for (int d = 0; d < DIM; ++d) m = fmaf(zq[d], e[d], m);
                float dd = __fmaf_rn(-2.f, m, zsq + sesq[k]);
                if (dd < best || (dd == best && k < bestk)) { best = dd; bestk = k; }
            }
        }
    }

    // merge lane pair: smaller exact d, tie -> smaller k (jnp first-min rule)
    {
        float ob = __shfl_xor_sync(0xffffffffu, best, 1);
        int   ok = __shfl_xor_sync(0xffffffffu, bestk, 1);
        if (ob < best || (ob == best && ok < bestk)) { best = ob; bestk = ok; }
    }

    // ---------------- outputs: stage quantized row halves into SC, loss partials
    float lsum = 0.f;
    {
        const float* eb = codebook + (size_t)bestk * DIM + half * 32;
        const float* zh = zq + half * 32;
        float* qrow = reinterpret_cast<float*>(smem + SM_SC + (uint32_t)lrow * RSS) + half * 32;
        #pragma unroll
        for (int i = 0; i < 8; ++i) {
            float d0 = eb[4 * i + 0] - zh[4 * i + 0];
            float d1 = eb[4 * i + 1] - zh[4 * i + 1];
            float d2 = eb[4 * i + 2] - zh[4 * i + 2];
            float d3 = eb[4 * i + 3] - zh[4 * i + 3];
            float4 qv = make_float4(zh[4 * i + 0] + d0, zh[4 * i + 1] + d1,
                                    zh[4 * i + 2] + d2, zh[4 * i + 3] + d3);
            *reinterpret_cast<float4*>(qrow + 4 * i) = qv;
            lsum = fmaf(d0, d0, lsum); lsum = fmaf(d1, d1, lsum);
            lsum = fmaf(d2, d2, lsum); lsum = fmaf(d3, d3, lsum);
        }
        if (half == 0) {
            out[OFF_I + r] = (float)bestk;
            atomicAdd(&g_counts[bestk], 1);   // spread-address REDG
        }
    }
    #pragma unroll
    for (int off = 16; off; off >>= 1)
        lsum += __shfl_down_sync(0xffffffffu, lsum, off);
    if (lane == 0) atomicAdd(&g_losssum, (double)lsum);

    // coalesced copy of quantized tile SC -> gmem
    __syncthreads();
    float* oq = out + OFF_Q + (size_t)row0 * DIM;
    #pragma unroll
    for (int i = tid; i < MTILE * (DIM / 4); i += TPB) {
        int rw = i >> 4, q = i & 15;
        float4 v = *reinterpret_cast<const float4*>(smem + SM_SC + (uint32_t)rw * RSS + q * 16);
        reinterpret_cast<float4*>(oq + (size_t)rw * DIM)[q] = v;
    }
}

// ---------------------------------------------------------------- finalize
__global__ void vq_final(float* __restrict__ out) {
    __shared__ double red[32];
    int t = threadIdx.x;  // 1024 threads
    float c = (float)g_counts[t];
    float p = c * (1.0f / 32768.0f);
    float term = p * logf(p + 1e-10f);
    double v = (double)term;
    #pragma unroll
    for (int off = 16; off; off >>= 1)
        v += __shfl_down_sync(0xffffffffu, v, off);
    if ((t & 31) == 0) red[t >> 5] = v;
    __syncthreads();
    if (t < 32) {
        double w = red[t];
        #pragma unroll
        for (int off = 16; off; off >>= 1)
            w += __shfl_down_sync(0xffffffffu, w, off);
        if (t == 0) {
            float s = (float)w;
            out[OFF_P] = expf(-s);
            float m = (float)(g_losssum * (1.0 / 2097152.0));
            out[OFF_L] = m + 0.25f * m;
        }
    }
}

// ---------------------------------------------------------------- launch
extern "C" void kernel_launch(void* const* d_in, const int* in_sizes, int n_in,
                              void* d_out, int out_size) {
    const float* z        = (const float*)d_in[0];
    const float* codebook = (const float*)d_in[1];
    float* out = (float*)d_out;

    cudaFuncSetAttribute(vq_main, cudaFuncAttributeMaxDynamicSharedMemorySize, SM_TOTAL);

    vq_prep_z<<<4096, 256>>>(z, 0);                       // idx 0
    vq_prep_z<<<4096, 256>>>(z, 1);                       // idx 1
    vq_prep_cb<<<256, 256>>>(codebook);                   // idx 2
    vq_main<<<NCTAS, TPB, SM_TOTAL>>>(z, codebook, out);  // idx 3 (ncu slot)
    vq_final<<<1, KCODES>>>(out);                         // idx 4
}